// round 4
// baseline (speedup 1.0000x reference)
#include <cuda_runtime.h>
#include <math.h>

// VoxelHuman fused kernel: embed + gather -> 3xTF32 MLP (mma.sync) -> compositing.
// One block = 2 rays = 128 points. Grid = B*R/2 = 8192 blocks, 256 threads.
// Accurate fp32 sincos (Cody-Waite) — immune to --use_fast_math MUFU reduction.

#define XS 264   // smem row stride (floats) for X / H1 buffer
#define BSS 264  // smem row stride for weight k-chunk staging

#define SMEM_FLOATS (128*XS + 8*BSS + 1024 + 512 + 192 + 256 + 256 + 8)

__device__ __forceinline__ void tf32split(float v, unsigned& hi, unsigned& lo) {
    unsigned h;
    asm("cvt.rna.tf32.f32 %0, %1;" : "=r"(h) : "f"(v));
    const float r = v - __uint_as_float(h);
    unsigned l;
    asm("cvt.rna.tf32.f32 %0, %1;" : "=r"(l) : "f"(r));
    hi = h; lo = l;
}

__device__ __forceinline__ void mma_tf32(float* c,
                                         unsigned a0, unsigned a1, unsigned a2, unsigned a3,
                                         unsigned b0, unsigned b1) {
    asm("mma.sync.aligned.m16n8k8.row.col.f32.tf32.tf32.f32 "
        "{%0,%1,%2,%3},{%4,%5,%6,%7},{%8,%9},{%0,%1,%2,%3};\n"
        : "+f"(c[0]), "+f"(c[1]), "+f"(c[2]), "+f"(c[3])
        : "r"(a0), "r"(a1), "r"(a2), "r"(a3), "r"(b0), "r"(b1));
}

// Accurate fp32 sincos: FMA Cody-Waite 3-term pi/2 reduction + minimax polys.
// Valid to ~1 ulp for |x| up to ~1e5 (our args are < ~4096).
__device__ __forceinline__ void sincos_acc(float x, float* sp, float* cp) {
    const float j = rintf(x * 0.636619772367581343f);   // 2/pi
    const int   q = (int)j;
    float r = fmaf(j, -1.57079637050628662109375f, x);  // -float(pi/2)
    r = fmaf(j,  4.37113882867379290e-08f, r);          // -(pi/2 - c1)
    r = fmaf(j,  1.71512451000590810e-15f, r);          // residual
    const float r2 = r * r;
    // sin poly on [-pi/4, pi/4]
    float sr = -1.9812813e-4f;
    sr = fmaf(sr, r2,  8.3333226e-3f);
    sr = fmaf(sr, r2, -1.6666667e-1f);
    sr = fmaf(sr * r2, r, r);
    // cos poly
    float cr =  2.4372668e-5f;
    cr = fmaf(cr, r2, -1.3887316e-3f);
    cr = fmaf(cr, r2,  4.1666646e-2f);
    cr = fmaf(cr, r2, -5.0000000e-1f);
    cr = fmaf(cr, r2,  1.0f);
    float ss = (q & 1) ? cr : sr;
    float cc = (q & 1) ? sr : cr;
    if (q & 2) ss = -ss;
    if (((q & 2) != 0) != ((q & 1) != 0)) cc = -cc;
    *sp = ss; *cp = cc;
}

__global__ void __launch_bounds__(256, 1)
vh_kernel(const float* __restrict__ rays_o, const float* __restrict__ rays_d,
          const float* __restrict__ uv_feat, const float* __restrict__ transforms,
          const float* __restrict__ w0, const float* __restrict__ b0,
          const float* __restrict__ w1, const float* __restrict__ b1,
          const float* __restrict__ w_out, const float* __restrict__ b_out,
          const int* __restrict__ uv_idx, const int* __restrict__ vox_idx,
          float* __restrict__ out)
{
    extern __shared__ float sm[];
    float* Xs    = sm;                 // 128 x XS  (X features fp32, reused as H1)
    float* Bst   = Xs + 128 * XS;      // 8 x BSS   (weight k-chunk, fp32)
    float* WoutS = Bst + 8 * BSS;      // 256*4
    float* rawS  = WoutS + 1024;       // 128*4
    float* TfS   = rawS + 512;         // 16*12
    float* b0S   = TfS + 192;          // 256
    float* b1S   = b0S + 256;          // 256
    float* boS   = b1S + 256;          // 4 (pad 8)

    const int tid  = threadIdx.x;
    const int lane = tid & 31;
    const int warp = tid >> 5;
    const int gid  = lane >> 2;   // group id 0..7
    const int tig  = lane & 3;    // thread-in-group 0..3
    const int mrow = warp * 16;   // this warp's 16-row strip

    // stage small constants
    for (int i = tid; i < 192; i += 256)  TfS[i]   = transforms[i];
    for (int i = tid; i < 1024; i += 256) WoutS[i] = w_out[i];
    b0S[tid] = b0[tid];
    b1S[tid] = b1[tid];
    if (tid < 4) boS[tid] = b_out[tid];
    __syncthreads();

    const int base = blockIdx.x * 128;   // flat (b,r,n) point base

    // ---------------- Phase 1: build X[128, 211] fp32 ----------------
    if (tid < 128) {
        // threads 0..127: transform + positional embedding (63 channels)
        const int p  = tid;
        const int lr = p >> 6, n = p & 63;
        const int g  = blockIdx.x * 2 + lr;
        const float z = 0.5f + (float)n * (1.5f / 64.0f);
        const float ox = rays_o[g*3+0], oy = rays_o[g*3+1], oz = rays_o[g*3+2];
        const float dx = rays_d[g*3+0], dy = rays_d[g*3+1], dz = rays_d[g*3+2];
        const float px = ox + dx * z, py = oy + dy * z, pz = oz + dz * z;
        const int vox = vox_idx[base + p];
        const float* T = TfS + vox * 12;
        const float pc0 = T[0]*px + T[1]*py + T[2]*pz  + T[3];
        const float pc1 = T[4]*px + T[5]*py + T[6]*pz  + T[7];
        const float pc2 = T[8]*px + T[9]*py + T[10]*pz + T[11];
        float* xr = Xs + p * XS;
        xr[0] = pc0; xr[1] = pc1; xr[2] = pc2;
        float f = 1.0f;
        #pragma unroll
        for (int k = 0; k < 10; ++k) {
            float s, c;
            sincos_acc(pc0 * f, &s, &c); xr[3+6*k+0] = s; xr[3+6*k+3] = c;
            sincos_acc(pc1 * f, &s, &c); xr[3+6*k+1] = s; xr[3+6*k+4] = c;
            sincos_acc(pc2 * f, &s, &c); xr[3+6*k+2] = s; xr[3+6*k+5] = c;
            f *= 2.0f;
        }
        #pragma unroll
        for (int c = 211; c < 216; ++c) xr[c] = 0.0f;  // K padding
    } else {
        // threads 128..255: gather uv_feat (148 ch) — 4 threads per point, float4
        const int t2  = tid - 128;
        const int sub = t2 & 3;
        #pragma unroll
        for (int pass = 0; pass < 4; ++pass) {
            const int p  = (t2 >> 2) + pass * 32;
            const int g  = blockIdx.x * 2 + (p >> 6);
            const int bi = g >> 13;
            const int uvi = uv_idx[base + p];
            const float4* src =
                (const float4*)(uv_feat + ((size_t)bi * 65536 + (size_t)uvi) * 148);
            float* xr = Xs + p * XS + 63;
            for (int q = sub; q < 37; q += 4) {
                const float4 v = src[q];
                xr[4*q+0] = v.x; xr[4*q+1] = v.y;
                xr[4*q+2] = v.z; xr[4*q+3] = v.w;
            }
        }
    }
    // (first __syncthreads inside the layer-0 loop fences phase 1)

    float acc[128];
    #pragma unroll
    for (int i = 0; i < 128; ++i) acc[i] = 0.0f;

    // ---------------- Layer 0: X[128,216] @ w0[216,256]  (3xTF32) ----------------
    for (int kc = 0; kc < 27; ++kc) {
        __syncthreads();
        #pragma unroll
        for (int i = 0; i < 8; ++i) {
            const int e = tid + i * 256;
            const int kk = e >> 8, nn = e & 255;
            const int krow = kc * 8 + kk;
            Bst[kk * BSS + nn] = (krow < 211) ? w0[krow * 256 + nn] : 0.0f;
        }
        __syncthreads();
        const float* xb = Xs + (mrow + gid) * XS + kc * 8;
        unsigned a0h,a0l,a1h,a1l,a2h,a2l,a3h,a3l;
        tf32split(xb[tig],           a0h, a0l);
        tf32split(xb[8*XS + tig],    a1h, a1l);
        tf32split(xb[tig + 4],       a2h, a2l);
        tf32split(xb[8*XS + tig+4],  a3h, a3l);
        #pragma unroll
        for (int j = 0; j < 32; ++j) {
            unsigned b0h,b0l,b1h,b1l;
            tf32split(Bst[tig * BSS + j * 8 + gid],       b0h, b0l);
            tf32split(Bst[(tig + 4) * BSS + j * 8 + gid], b1h, b1l);
            mma_tf32(&acc[4*j], a0h, a1h, a2h, a3h, b0h, b1h);
            mma_tf32(&acc[4*j], a0h, a1h, a2h, a3h, b0l, b1l);
            mma_tf32(&acc[4*j], a0l, a1l, a2l, a3l, b0h, b1h);
        }
    }

    // relu(+b0), write H1 (fp32) into Xs (each warp overwrites only its own rows)
    {
        float* hr = Xs + (mrow + gid) * XS;
        #pragma unroll
        for (int j = 0; j < 32; ++j) {
            const int c0 = j * 8 + tig * 2;
            const float v0 = fmaxf(acc[4*j+0] + b0S[c0],   0.0f);
            const float v1 = fmaxf(acc[4*j+1] + b0S[c0+1], 0.0f);
            const float v2 = fmaxf(acc[4*j+2] + b0S[c0],   0.0f);
            const float v3 = fmaxf(acc[4*j+3] + b0S[c0+1], 0.0f);
            hr[c0]        = v0; hr[c0+1]        = v1;
            hr[8*XS + c0] = v2; hr[8*XS + c0+1] = v3;
            acc[4*j+0] = 0.0f; acc[4*j+1] = 0.0f; acc[4*j+2] = 0.0f; acc[4*j+3] = 0.0f;
        }
    }

    // ---------------- Layer 1: H1[128,256] @ w1[256,256]  (3xTF32) ----------------
    for (int kc = 0; kc < 32; ++kc) {
        __syncthreads();
        #pragma unroll
        for (int i = 0; i < 8; ++i) {
            const int e = tid + i * 256;
            const int kk = e >> 8, nn = e & 255;
            Bst[kk * BSS + nn] = w1[(kc * 8 + kk) * 256 + nn];
        }
        __syncthreads();
        const float* xb = Xs + (mrow + gid) * XS + kc * 8;
        unsigned a0h,a0l,a1h,a1l,a2h,a2l,a3h,a3l;
        tf32split(xb[tig],           a0h, a0l);
        tf32split(xb[8*XS + tig],    a1h, a1l);
        tf32split(xb[tig + 4],       a2h, a2l);
        tf32split(xb[8*XS + tig+4],  a3h, a3l);
        #pragma unroll
        for (int j = 0; j < 32; ++j) {
            unsigned b0h,b0l,b1h,b1l;
            tf32split(Bst[tig * BSS + j * 8 + gid],       b0h, b0l);
            tf32split(Bst[(tig + 4) * BSS + j * 8 + gid], b1h, b1l);
            mma_tf32(&acc[4*j], a0h, a1h, a2h, a3h, b0h, b1h);
            mma_tf32(&acc[4*j], a0h, a1h, a2h, a3h, b0l, b1l);
            mma_tf32(&acc[4*j], a0l, a1l, a2l, a3l, b0h, b1h);
        }
    }

    // ---------------- Layer 2 (fp32): H2[128,256] @ w_out[256,4] ----------------
    {
        float pA[4] = {0,0,0,0}, pB[4] = {0,0,0,0};
        #pragma unroll
        for (int j = 0; j < 32; ++j) {
            const int c0 = j * 8 + tig * 2;
            const float h00 = fmaxf(acc[4*j+0] + b1S[c0],   0.0f);
            const float h01 = fmaxf(acc[4*j+1] + b1S[c0+1], 0.0f);
            const float h10 = fmaxf(acc[4*j+2] + b1S[c0],   0.0f);
            const float h11 = fmaxf(acc[4*j+3] + b1S[c0+1], 0.0f);
            #pragma unroll
            for (int o = 0; o < 4; ++o) {
                const float wv0 = WoutS[c0 * 4 + o];
                const float wv1 = WoutS[(c0 + 1) * 4 + o];
                pA[o] += h00 * wv0 + h01 * wv1;
                pB[o] += h10 * wv0 + h11 * wv1;
            }
        }
        #pragma unroll
        for (int m = 1; m <= 2; m <<= 1) {
            #pragma unroll
            for (int o = 0; o < 4; ++o) {
                pA[o] += __shfl_xor_sync(0xffffffffu, pA[o], m);
                pB[o] += __shfl_xor_sync(0xffffffffu, pB[o], m);
            }
        }
        if (tig == 0) {
            const int rA = mrow + gid;
            #pragma unroll
            for (int o = 0; o < 4; ++o) {
                rawS[rA * 4 + o]       = pA[o] + boS[o];
                rawS[(rA + 8) * 4 + o] = pB[o] + boS[o];
            }
        }
    }
    __syncthreads();

    // ---------------- Compositing: one thread per ray ----------------
    if (tid < 2) {
        const int g = blockIdx.x * 2 + tid;
        const float dx = rays_d[g*3], dy = rays_d[g*3+1], dz = rays_d[g*3+2];
        const float nd = sqrtf(dx*dx + dy*dy + dz*dz);
        float trans = 1.0f, r0 = 0.0f, r1 = 0.0f, r2 = 0.0f;
        const float ddist = 1.5f / 64.0f;
        for (int n = 0; n < 64; ++n) {
            const float* rw = rawS + (tid * 64 + n) * 4;
            const float sigma = fmaxf(rw[3], 0.0f);
            const float dist  = (n == 63) ? 1e10f : ddist;
            const float alpha = 1.0f - expf(-sigma * dist * nd);
            const float wgt   = alpha * trans;
            trans = trans * (1.0f - alpha + 1e-10f);
            r0 += wgt / (1.0f + expf(-rw[0]));
            r1 += wgt / (1.0f + expf(-rw[1]));
            r2 += wgt / (1.0f + expf(-rw[2]));
        }
        out[g*3+0] = r0; out[g*3+1] = r1; out[g*3+2] = r2;
    }
}

extern "C" void kernel_launch(void* const* d_in, const int* in_sizes, int n_in,
                              void* d_out, int out_size)
{
    const float* rays_o     = (const float*)d_in[0];
    const float* rays_d     = (const float*)d_in[1];
    const float* uv_feat    = (const float*)d_in[2];
    const float* transforms = (const float*)d_in[3];
    const float* w0         = (const float*)d_in[4];
    const float* b0         = (const float*)d_in[5];
    const float* w1         = (const float*)d_in[6];
    const float* b1         = (const float*)d_in[7];
    const float* w_out      = (const float*)d_in[8];
    const float* b_out      = (const float*)d_in[9];
    const int*   uv_idx     = (const int*)d_in[10];
    const int*   vox_idx    = (const int*)d_in[11];
    float* out = (float*)d_out;

    const size_t smem = (size_t)SMEM_FLOATS * sizeof(float);
    cudaFuncSetAttribute(vh_kernel, cudaFuncAttributeMaxDynamicSharedMemorySize, (int)smem);

    vh_kernel<<<8192, 256, smem>>>(rays_o, rays_d, uv_feat, transforms,
                                   w0, b0, w1, b1, w_out, b_out,
                                   uv_idx, vox_idx, out);
}

// round 6
// speedup vs baseline: 1.5124x; 1.5124x over previous
#include <cuda_runtime.h>
#include <cuda_fp16.h>
#include <math.h>

// VoxelHuman fused: embed + gather -> 3xFP16 (m16n8k16) MLP -> compositing.
// One block = 2 rays = 128 points. Grid 8192, 512 threads (16 warps).
// Warp tile: 16 rows x 128 cols. B pre-split hi/lo f16x2 in smem at staging.
// fp16 3-term split: dropped lo*lo term ~2^-22 per product (== 3xTF32 accuracy).

#define XS 264          // X/H1 row stride (floats)
#define NPAIR 2048      // pairs per 16-k weight chunk (8 kp x 256 n)

#define SMEM_FLOATS (128*XS + 2*NPAIR + 1024 + 1024 + 192 + 256 + 256 + 8)

__device__ __forceinline__ unsigned pack_f16x2(float hi, float lo) {
    unsigned d;
    asm("cvt.rn.f16x2.f32 %0, %1, %2;" : "=r"(d) : "f"(hi), "f"(lo));
    return d;
}

// v0 -> low half (even k), v1 -> high half (odd k); hi = f16 pair, lo = residual pair
__device__ __forceinline__ void split_pair(float v0, float v1, unsigned& hi, unsigned& lo) {
    const unsigned h = pack_f16x2(v1, v0);
    const __half2 hh = *reinterpret_cast<const __half2*>(&h);
    const float f0 = __low2float(hh);
    const float f1 = __high2float(hh);
    lo = pack_f16x2(v1 - f1, v0 - f0);
    hi = h;
}

__device__ __forceinline__ void mma_f16(float* c,
                                        unsigned a0, unsigned a1, unsigned a2, unsigned a3,
                                        unsigned b0, unsigned b1) {
    asm("mma.sync.aligned.m16n8k16.row.col.f32.f16.f16.f32 "
        "{%0,%1,%2,%3},{%4,%5,%6,%7},{%8,%9},{%0,%1,%2,%3};\n"
        : "+f"(c[0]), "+f"(c[1]), "+f"(c[2]), "+f"(c[3])
        : "r"(a0), "r"(a1), "r"(a2), "r"(a3), "r"(b0), "r"(b1));
}

// Accurate fp32 sincos (Cody-Waite) — immune to --use_fast_math MUFU reduction.
__device__ __forceinline__ void sincos_acc(float x, float* sp, float* cp) {
    const float j = rintf(x * 0.636619772367581343f);
    const int   q = (int)j;
    float r = fmaf(j, -1.57079637050628662109375f, x);
    r = fmaf(j,  4.37113882867379290e-08f, r);
    r = fmaf(j,  1.71512451000590810e-15f, r);
    const float r2 = r * r;
    float sr = -1.9812813e-4f;
    sr = fmaf(sr, r2,  8.3333226e-3f);
    sr = fmaf(sr, r2, -1.6666667e-1f);
    sr = fmaf(sr * r2, r, r);
    float cr =  2.4372668e-5f;
    cr = fmaf(cr, r2, -1.3887316e-3f);
    cr = fmaf(cr, r2,  4.1666646e-2f);
    cr = fmaf(cr, r2, -5.0000000e-1f);
    cr = fmaf(cr, r2,  1.0f);
    float ss = (q & 1) ? cr : sr;
    float cc = (q & 1) ? sr : cr;
    if (q & 2) ss = -ss;
    if (((q & 2) != 0) != ((q & 1) != 0)) cc = -cc;
    *sp = ss; *cp = cc;
}

__global__ void __launch_bounds__(512, 1)
vh_kernel(const float* __restrict__ rays_o, const float* __restrict__ rays_d,
          const float* __restrict__ uv_feat, const float* __restrict__ transforms,
          const float* __restrict__ w0, const float* __restrict__ b0,
          const float* __restrict__ w1, const float* __restrict__ b1,
          const float* __restrict__ w_out, const float* __restrict__ b_out,
          const int* __restrict__ uv_idx, const int* __restrict__ vox_idx,
          float* __restrict__ out)
{
    extern __shared__ float sm[];
    float*    Xs    = sm;                              // 128 x XS fp32 (X, then H1)
    unsigned* BhiS  = (unsigned*)(Xs + 128 * XS);      // 2048 f16x2 pairs (hi)
    unsigned* BloS  = BhiS + NPAIR;                    // 2048 (lo)
    float*    WoutS = (float*)(BloS + NPAIR);          // 1024
    float*    rawS  = WoutS + 1024;                    // 2 x 128 x 4
    float*    TfS   = rawS + 1024;                     // 192
    float*    b0S   = TfS + 192;                       // 256
    float*    b1S   = b0S + 256;                       // 256
    float*    boS   = b1S + 256;                       // 4 (pad 8)

    const int tid   = threadIdx.x;
    const int lane  = tid & 31;
    const int warp  = tid >> 5;            // 0..15
    const int gid   = lane >> 2;
    const int tig   = lane & 3;
    const int mrow  = (warp >> 1) * 16;    // 16-row strip
    const int nhalf = (warp & 1) * 128;    // 128-col half

    // stage small constants
    for (int i = tid; i < 192;  i += 512) TfS[i]   = transforms[i];
    for (int i = tid; i < 1024; i += 512) WoutS[i] = w_out[i];
    if (tid < 256) { b0S[tid] = b0[tid]; b1S[tid] = b1[tid]; }
    if (tid < 4) boS[tid] = b_out[tid];
    __syncthreads();

    const int base = blockIdx.x * 128;

    // prefetch weight chunk 0 of layer 0 into registers (lands during phase 1)
    float pv0[4], pv1[4];
    {
        #pragma unroll
        for (int i = 0; i < 4; ++i) {
            const int pr = tid + i * 512;
            const int col = pr >> 3, slot = pr & 7;
            const int kp = (slot >> 1) + ((slot & 1) << 2);
            const int k0 = 2 * kp;
            pv0[i] = (k0     < 211) ? w0[k0 * 256 + col]       : 0.0f;
            pv1[i] = (k0 + 1 < 211) ? w0[(k0 + 1) * 256 + col] : 0.0f;
        }
    }

    // ---------------- Phase 1: build X[128, 211] fp32 (pad to 224) ----------------
    if (tid < 128) {
        const int p  = tid;
        const int n  = p & 63;
        const int g  = blockIdx.x * 2 + (p >> 6);
        const float z = 0.5f + (float)n * (1.5f / 64.0f);
        const float px = rays_o[g*3+0] + rays_d[g*3+0] * z;
        const float py = rays_o[g*3+1] + rays_d[g*3+1] * z;
        const float pz = rays_o[g*3+2] + rays_d[g*3+2] * z;
        const int vox = vox_idx[base + p];
        const float* T = TfS + vox * 12;
        const float pc0 = T[0]*px + T[1]*py + T[2]*pz  + T[3];
        const float pc1 = T[4]*px + T[5]*py + T[6]*pz  + T[7];
        const float pc2 = T[8]*px + T[9]*py + T[10]*pz + T[11];
        float* xr = Xs + p * XS;
        xr[0] = pc0; xr[1] = pc1; xr[2] = pc2;
        float f = 1.0f;
        #pragma unroll
        for (int k = 0; k < 10; ++k) {
            float s, c;
            sincos_acc(pc0 * f, &s, &c); xr[3+6*k+0] = s; xr[3+6*k+3] = c;
            sincos_acc(pc1 * f, &s, &c); xr[3+6*k+1] = s; xr[3+6*k+4] = c;
            sincos_acc(pc2 * f, &s, &c); xr[3+6*k+2] = s; xr[3+6*k+5] = c;
            f *= 2.0f;
        }
        #pragma unroll
        for (int c = 211; c < 224; ++c) xr[c] = 0.0f;
    } else {
        // 384 threads gather uv_feat (148 ch): 3 threads per point
        const int t3  = tid - 128;
        const int p   = t3 & 127;
        const int sub = t3 >> 7;       // 0..2
        const int g   = blockIdx.x * 2 + (p >> 6);
        const int bi  = g >> 13;
        const int uvi = uv_idx[base + p];
        const float4* src =
            (const float4*)(uv_feat + ((size_t)bi * 65536 + (size_t)uvi) * 148);
        float* xr = Xs + p * XS + 63;
        for (int q = sub; q < 37; q += 3) {
            const float4 v = src[q];
            xr[4*q+0] = v.x; xr[4*q+1] = v.y; xr[4*q+2] = v.z; xr[4*q+3] = v.w;
        }
    }

    float acc[64];
    #pragma unroll
    for (int i = 0; i < 64; ++i) acc[i] = 0.0f;

    // ================= Layer 0: X[128,224] @ w0 (14 chunks of k16) =================
    for (int kc = 0; kc < 14; ++kc) {
        __syncthreads();   // prev chunk consumed (kc=0: phase-1 writes done)
        // store prefetched chunk (split to hi/lo f16x2)
        #pragma unroll
        for (int i = 0; i < 4; ++i) {
            const int pr = tid + i * 512;
            unsigned h, l;
            split_pair(pv0[i], pv1[i], h, l);
            BhiS[pr] = h; BloS[pr] = l;
        }
        // prefetch next chunk (last layer-0 chunk prefetches layer-1 chunk 0)
        {
            const int nk = kc + 1;
            const float* W = (nk < 14) ? w0 : w1;
            const int kb   = (nk < 14) ? nk * 16 : 0;
            const int kmax = (nk < 14) ? 211 : 256;
            #pragma unroll
            for (int i = 0; i < 4; ++i) {
                const int pr = tid + i * 512;
                const int col = pr >> 3, slot = pr & 7;
                const int kp = (slot >> 1) + ((slot & 1) << 2);
                const int k0 = kb + 2 * kp;
                pv0[i] = (k0     < kmax) ? W[k0 * 256 + col]       : 0.0f;
                pv1[i] = (k0 + 1 < kmax) ? W[(k0 + 1) * 256 + col] : 0.0f;
            }
        }
        __syncthreads();
        // A fragments (fp32 -> f16 hi/lo, own rows only)
        const float2* xb0 = (const float2*)(Xs + (mrow + gid) * XS + kc * 16);
        const float2* xb1 = (const float2*)(Xs + (mrow + gid + 8) * XS + kc * 16);
        const float2 v0 = xb0[tig], v2 = xb0[4 + tig];
        const float2 v1 = xb1[tig], v3 = xb1[4 + tig];
        unsigned a0h,a0l,a1h,a1l,a2h,a2l,a3h,a3l;
        split_pair(v0.x, v0.y, a0h, a0l);
        split_pair(v1.x, v1.y, a1h, a1l);
        split_pair(v2.x, v2.y, a2h, a2l);
        split_pair(v3.x, v3.y, a3h, a3l);
        #pragma unroll
        for (int j = 0; j < 16; ++j) {
            const int col = nhalf + j * 8 + gid;
            const uint2 bh = ((const uint2*)BhiS)[col * 4 + tig];
            const uint2 bl = ((const uint2*)BloS)[col * 4 + tig];
            mma_f16(&acc[4*j], a0h, a1h, a2h, a3h, bh.x, bh.y);
            mma_f16(&acc[4*j], a0h, a1h, a2h, a3h, bl.x, bl.y);
            mma_f16(&acc[4*j], a0l, a1l, a2l, a3l, bh.x, bh.y);
        }
    }

    // relu(+b0) -> H1 into Xs (own rows, own col half)
    __syncthreads();   // partner warp may still read X rows
    {
        float* hr = Xs + (mrow + gid) * XS;
        #pragma unroll
        for (int j = 0; j < 16; ++j) {
            const int gc = nhalf + j * 8 + tig * 2;
            hr[gc]          = fmaxf(acc[4*j+0] + b0S[gc],   0.0f);
            hr[gc+1]        = fmaxf(acc[4*j+1] + b0S[gc+1], 0.0f);
            hr[8*XS + gc]   = fmaxf(acc[4*j+2] + b0S[gc],   0.0f);
            hr[8*XS + gc+1] = fmaxf(acc[4*j+3] + b0S[gc+1], 0.0f);
            acc[4*j+0] = 0.0f; acc[4*j+1] = 0.0f; acc[4*j+2] = 0.0f; acc[4*j+3] = 0.0f;
        }
    }

    // ================= Layer 1: H1[128,256] @ w1 (16 chunks) =================
    for (int kc = 0; kc < 16; ++kc) {
        __syncthreads();   // kc=0: H1 writes done; else prev chunk consumed
        #pragma unroll
        for (int i = 0; i < 4; ++i) {
            const int pr = tid + i * 512;
            unsigned h, l;
            split_pair(pv0[i], pv1[i], h, l);
            BhiS[pr] = h; BloS[pr] = l;
        }
        if (kc + 1 < 16) {
            #pragma unroll
            for (int i = 0; i < 4; ++i) {
                const int pr = tid + i * 512;
                const int col = pr >> 3, slot = pr & 7;
                const int kp = (slot >> 1) + ((slot & 1) << 2);
                const int k0 = (kc + 1) * 16 + 2 * kp;
                pv0[i] = w1[k0 * 256 + col];
                pv1[i] = w1[(k0 + 1) * 256 + col];
            }
        }
        __syncthreads();
        const float2* xb0 = (const float2*)(Xs + (mrow + gid) * XS + kc * 16);
        const float2* xb1 = (const float2*)(Xs + (mrow + gid + 8) * XS + kc * 16);
        const float2 v0 = xb0[tig], v2 = xb0[4 + tig];
        const float2 v1 = xb1[tig], v3 = xb1[4 + tig];
        unsigned a0h,a0l,a1h,a1l,a2h,a2l,a3h,a3l;
        split_pair(v0.x, v0.y, a0h, a0l);
        split_pair(v1.x, v1.y, a1h, a1l);
        split_pair(v2.x, v2.y, a2h, a2l);
        split_pair(v3.x, v3.y, a3h, a3l);
        #pragma unroll
        for (int j = 0; j < 16; ++j) {
            const int col = nhalf + j * 8 + gid;
            const uint2 bh = ((const uint2*)BhiS)[col * 4 + tig];
            const uint2 bl = ((const uint2*)BloS)[col * 4 + tig];
            mma_f16(&acc[4*j], a0h, a1h, a2h, a3h, bh.x, bh.y);
            mma_f16(&acc[4*j], a0h, a1h, a2h, a3h, bl.x, bl.y);
            mma_f16(&acc[4*j], a0l, a1l, a2l, a3l, bh.x, bh.y);
        }
    }

    // ========== Layer 2 (fp32): relu(+b1) then @ w_out[256,4], half-partials ==========
    {
        float pA[4] = {0,0,0,0}, pB[4] = {0,0,0,0};
        #pragma unroll
        for (int j = 0; j < 16; ++j) {
            const int gc = nhalf + j * 8 + tig * 2;
            const float h00 = fmaxf(acc[4*j+0] + b1S[gc],   0.0f);
            const float h01 = fmaxf(acc[4*j+1] + b1S[gc+1], 0.0f);
            const float h10 = fmaxf(acc[4*j+2] + b1S[gc],   0.0f);
            const float h11 = fmaxf(acc[4*j+3] + b1S[gc+1], 0.0f);
            #pragma unroll
            for (int o = 0; o < 4; ++o) {
                const float wv0 = WoutS[gc * 4 + o];
                const float wv1 = WoutS[(gc + 1) * 4 + o];
                pA[o] += h00 * wv0 + h01 * wv1;
                pB[o] += h10 * wv0 + h11 * wv1;
            }
        }
        #pragma unroll
        for (int m = 1; m <= 2; m <<= 1) {
            #pragma unroll
            for (int o = 0; o < 4; ++o) {
                pA[o] += __shfl_xor_sync(0xffffffffu, pA[o], m);
                pB[o] += __shfl_xor_sync(0xffffffffu, pB[o], m);
            }
        }
        if (tig == 0) {
            const int half = warp & 1;
            const int rA = mrow + gid;
            #pragma unroll
            for (int o = 0; o < 4; ++o) {
                rawS[half*512 + rA * 4 + o]       = pA[o];
                rawS[half*512 + (rA + 8) * 4 + o] = pB[o];
            }
        }
    }
    __syncthreads();

    // ---------------- Compositing: one thread per ray ----------------
    if (tid < 2) {
        const int g = blockIdx.x * 2 + tid;
        const float dx = rays_d[g*3], dy = rays_d[g*3+1], dz = rays_d[g*3+2];
        const float nd = sqrtf(dx*dx + dy*dy + dz*dz);
        float trans = 1.0f, r0 = 0.0f, r1 = 0.0f, r2 = 0.0f;
        const float ddist = 1.5f / 64.0f;
        for (int n = 0; n < 64; ++n) {
            const int row = tid * 64 + n;
            const float raw0 = rawS[row*4+0] + rawS[512 + row*4+0] + boS[0];
            const float raw1 = rawS[row*4+1] + rawS[512 + row*4+1] + boS[1];
            const float raw2 = rawS[row*4+2] + rawS[512 + row*4+2] + boS[2];
            const float raw3 = rawS[row*4+3] + rawS[512 + row*4+3] + boS[3];
            const float sigma = fmaxf(raw3, 0.0f);
            const float dist  = (n == 63) ? 1e10f : ddist;
            const float alpha = 1.0f - expf(-sigma * dist * nd);
            const float wgt   = alpha * trans;
            trans = trans * (1.0f - alpha + 1e-10f);
            r0 += wgt / (1.0f + expf(-raw0));
            r1 += wgt / (1.0f + expf(-raw1));
            r2 += wgt / (1.0f + expf(-raw2));
        }
        out[g*3+0] = r0; out[g*3+1] = r1; out[g*3+2] = r2;
    }
}

extern "C" void kernel_launch(void* const* d_in, const int* in_sizes, int n_in,
                              void* d_out, int out_size)
{
    const float* rays_o     = (const float*)d_in[0];
    const float* rays_d     = (const float*)d_in[1];
    const float* uv_feat    = (const float*)d_in[2];
    const float* transforms = (const float*)d_in[3];
    const float* w0         = (const float*)d_in[4];
    const float* b0         = (const float*)d_in[5];
    const float* w1         = (const float*)d_in[6];
    const float* b1         = (const float*)d_in[7];
    const float* w_out      = (const float*)d_in[8];
    const float* b_out      = (const float*)d_in[9];
    const int*   uv_idx     = (const int*)d_in[10];
    const int*   vox_idx    = (const int*)d_in[11];
    float* out = (float*)d_out;

    const size_t smem = (size_t)SMEM_FLOATS * sizeof(float);
    cudaFuncSetAttribute(vh_kernel, cudaFuncAttributeMaxDynamicSharedMemorySize, (int)smem);

    vh_kernel<<<8192, 512, smem>>>(rays_o, rays_d, uv_feat, transforms,
                                   w0, b0, w1, b1, w_out, b_out,
                                   uv_idx, vox_idx, out);
}

// round 7
// speedup vs baseline: 1.5258x; 1.0089x over previous
#include <cuda_runtime.h>
#include <cuda_fp16.h>
#include <math.h>

// VoxelHuman fused: embed + gather -> 3xFP16 (m16n8k16) MLP -> compositing.
// Block = 2 rays = 128 points; grid 8192; 512 threads (16 warps).
// Warp tile 32x64 (4 row-groups x 4 col-groups). X/H1 stored pre-split f16 hi/lo.
// Weights: coalesced float4 prefetch -> double-buffered hi/lo staging, 1 sync/chunk.

#define SU2 132            // X2 row stride (uint2)
#define BST 268            // B buffer slot stride (uint2)
#define BBUF (8*BST)       // uint2 per B buffer

#define SMEM_BYTES (128*SU2*8 + 2*BBUF*8 + 4096 + 8192 + 768 + 1024 + 1024 + 32)

__device__ __forceinline__ unsigned pack_f16x2(float hi, float lo) {
    unsigned d;
    asm("cvt.rn.f16x2.f32 %0, %1, %2;" : "=r"(d) : "f"(hi), "f"(lo));
    return d;
}

// v0 -> low half (even k), v1 -> high half (odd k)
__device__ __forceinline__ void split_pair(float v0, float v1, unsigned& hi, unsigned& lo) {
    const unsigned h = pack_f16x2(v1, v0);
    const __half2 hh = *reinterpret_cast<const __half2*>(&h);
    const float f0 = __low2float(hh);
    const float f1 = __high2float(hh);
    lo = pack_f16x2(v1 - f1, v0 - f0);
    hi = h;
}

__device__ __forceinline__ void mma_f16(float* c,
                                        unsigned a0, unsigned a1, unsigned a2, unsigned a3,
                                        unsigned b0, unsigned b1) {
    asm("mma.sync.aligned.m16n8k16.row.col.f32.f16.f16.f32 "
        "{%0,%1,%2,%3},{%4,%5,%6,%7},{%8,%9},{%0,%1,%2,%3};\n"
        : "+f"(c[0]), "+f"(c[1]), "+f"(c[2]), "+f"(c[3])
        : "r"(a0), "r"(a1), "r"(a2), "r"(a3), "r"(b0), "r"(b1));
}

// Accurate fp32 sincos (Cody-Waite) — immune to --use_fast_math MUFU reduction.
__device__ __forceinline__ void sincos_acc(float x, float* sp, float* cp) {
    const float j = rintf(x * 0.636619772367581343f);
    const int   q = (int)j;
    float r = fmaf(j, -1.57079637050628662109375f, x);
    r = fmaf(j,  4.37113882867379290e-08f, r);
    r = fmaf(j,  1.71512451000590810e-15f, r);
    const float r2 = r * r;
    float sr = -1.9812813e-4f;
    sr = fmaf(sr, r2,  8.3333226e-3f);
    sr = fmaf(sr, r2, -1.6666667e-1f);
    sr = fmaf(sr * r2, r, r);
    float cr =  2.4372668e-5f;
    cr = fmaf(cr, r2, -1.3887316e-3f);
    cr = fmaf(cr, r2,  4.1666646e-2f);
    cr = fmaf(cr, r2, -5.0000000e-1f);
    cr = fmaf(cr, r2,  1.0f);
    float ss = (q & 1) ? cr : sr;
    float cc = (q & 1) ? sr : cr;
    if (q & 2) ss = -ss;
    if (((q & 2) != 0) != ((q & 1) != 0)) cc = -cc;
    *sp = ss; *cp = cc;
}

__global__ void __launch_bounds__(512, 1)
vh_kernel(const float* __restrict__ rays_o, const float* __restrict__ rays_d,
          const float* __restrict__ uv_feat, const float* __restrict__ transforms,
          const float* __restrict__ w0, const float* __restrict__ b0,
          const float* __restrict__ w1, const float* __restrict__ b1,
          const float* __restrict__ w_out, const float* __restrict__ b_out,
          const int* __restrict__ uv_idx, const int* __restrict__ vox_idx,
          float* __restrict__ out)
{
    extern __shared__ char smraw[];
    uint2* X2    = (uint2*)smraw;               // 128 x SU2 {hi,lo} f16x2 pairs
    uint2* Bb    = X2 + 128 * SU2;              // [2][8][BST] {hi,lo}
    float* WoutS = (float*)(Bb + 2 * BBUF);     // 1024
    float* rawS  = WoutS + 1024;                // 4 x 128 x 4
    float* TfS   = rawS + 2048;                 // 192
    float* b0S   = TfS + 192;                   // 256
    float* b1S   = b0S + 256;                   // 256
    float* boS   = b1S + 256;                   // 4 (pad 8)

    const int tid  = threadIdx.x;
    const int lane = tid & 31;
    const int warp = tid >> 5;           // 0..15
    const int gid  = lane >> 2;
    const int tig  = lane & 3;
    const int mrow = (warp >> 2) * 32;   // 32-row group
    const int nq   = (warp & 3) * 64;    // 64-col group

    const int kp   = tid >> 6;           // weight k-pair 0..7
    const int col4 = tid & 63;           // weight col-quad

    // stage small constants
    for (int i = tid; i < 192;  i += 512) TfS[i]   = transforms[i];
    for (int i = tid; i < 1024; i += 512) WoutS[i] = w_out[i];
    if (tid < 256) { b0S[tid] = b0[tid]; b1S[tid] = b1[tid]; }
    if (tid < 4) boS[tid] = b_out[tid];
    __syncthreads();

    const int base = blockIdx.x * 128;

    // ---- weight fetch helpers ----
    // smem k layout for layer 0: [0..62]=w0 rows 0..62, 63=zero, [64..211]=w0 rows 63..210, rest zero
    auto ldw0 = [&](int k) -> float4 {
        if (k < 63)  return ((const float4*)(w0 + (size_t)k * 256))[col4];
        if (k >= 64 && k < 212) return ((const float4*)(w0 + (size_t)(k - 1) * 256))[col4];
        return make_float4(0.f, 0.f, 0.f, 0.f);
    };

    float4 q0, q1;   // prefetched next chunk (rows k0, k0+1 of chunk)
    // prefetch chunk 0 (layer 0)
    q0 = ldw0(2 * kp);
    q1 = ldw0(2 * kp + 1);

    // ---------------- Phase 1: build X (pre-split hi/lo pairs) ----------------
    if (tid < 128) {
        const int p = tid;
        const int n = p & 63;
        const int g = blockIdx.x * 2 + (p >> 6);
        const float z = 0.5f + (float)n * (1.5f / 64.0f);
        const float px = rays_o[g*3+0] + rays_d[g*3+0] * z;
        const float py = rays_o[g*3+1] + rays_d[g*3+1] * z;
        const float pz = rays_o[g*3+2] + rays_d[g*3+2] * z;
        const int vox = vox_idx[base + p];
        const float* T = TfS + vox * 12;
        float xv[64];
        xv[0] = T[0]*px + T[1]*py + T[2]*pz  + T[3];
        xv[1] = T[4]*px + T[5]*py + T[6]*pz  + T[7];
        xv[2] = T[8]*px + T[9]*py + T[10]*pz + T[11];
        float f = 1.0f;
        #pragma unroll
        for (int k = 0; k < 10; ++k) {
            float s, c;
            sincos_acc(xv[0] * f, &s, &c); xv[3+6*k+0] = s; xv[3+6*k+3] = c;
            sincos_acc(xv[1] * f, &s, &c); xv[3+6*k+1] = s; xv[3+6*k+4] = c;
            sincos_acc(xv[2] * f, &s, &c); xv[3+6*k+2] = s; xv[3+6*k+5] = c;
            f *= 2.0f;
        }
        xv[63] = 0.0f;
        uint2* xr = X2 + p * SU2;
        #pragma unroll
        for (int q = 0; q < 32; ++q) {
            unsigned h, l;
            split_pair(xv[2*q], xv[2*q+1], h, l);
            xr[q] = make_uint2(h, l);
        }
        #pragma unroll
        for (int q = 106; q < 112; ++q) xr[q] = make_uint2(0u, 0u);
    } else {
        // 384 threads gather uv_feat (148 ch): 3 threads per point, split+store pairs
        const int t3  = tid - 128;
        const int p   = t3 & 127;
        const int sub = t3 >> 7;
        const int g   = blockIdx.x * 2 + (p >> 6);
        const int bi  = g >> 13;
        const int uvi = uv_idx[base + p];
        const float4* src =
            (const float4*)(uv_feat + ((size_t)bi * 65536 + (size_t)uvi) * 148);
        uint2* xr = X2 + p * SU2;
        for (int q = sub; q < 37; q += 3) {
            const float4 v = src[q];
            unsigned h0, l0, h1, l1;
            split_pair(v.x, v.y, h0, l0);
            split_pair(v.z, v.w, h1, l1);
            *(uint4*)(xr + 32 + 2 * q) = make_uint4(h0, l0, h1, l1);
        }
    }

    // stage chunk 0 into buf 0
    {
        unsigned h0,l0,h1,l1,h2,l2,h3,l3;
        split_pair(q0.x, q1.x, h0, l0);
        split_pair(q0.y, q1.y, h1, l1);
        split_pair(q0.z, q1.z, h2, l2);
        split_pair(q0.w, q1.w, h3, l3);
        uint4* dst = (uint4*)(Bb + kp * BST + col4 * 4);
        dst[0] = make_uint4(h0, l0, h1, l1);
        dst[1] = make_uint4(h2, l2, h3, l3);
    }
    // prefetch chunk 1
    q0 = ldw0(16 + 2 * kp);
    q1 = ldw0(16 + 2 * kp + 1);

    float acc[64];
    #pragma unroll
    for (int i = 0; i < 64; ++i) acc[i] = 0.0f;

    __syncthreads();

    // ================= Unified chunk loop: 14 (layer0) + 16 (layer1) =================
    #pragma unroll 1
    for (int c = 0; c < 30; ++c) {
        // stage prefetched chunk c+1 into the other buffer
        if (c < 29) {
            unsigned h0,l0,h1,l1,h2,l2,h3,l3;
            split_pair(q0.x, q1.x, h0, l0);
            split_pair(q0.y, q1.y, h1, l1);
            split_pair(q0.z, q1.z, h2, l2);
            split_pair(q0.w, q1.w, h3, l3);
            uint4* dst = (uint4*)(Bb + ((c + 1) & 1) * BBUF + kp * BST + col4 * 4);
            dst[0] = make_uint4(h0, l0, h1, l1);
            dst[1] = make_uint4(h2, l2, h3, l3);
        }
        // prefetch chunk c+2
        if (c < 28) {
            const int nc = c + 2;
            if (nc < 14) {
                q0 = ldw0(nc * 16 + 2 * kp);
                q1 = ldw0(nc * 16 + 2 * kp + 1);
            } else {
                const int k0 = (nc - 14) * 16 + 2 * kp;
                q0 = ((const float4*)(w1 + (size_t)k0 * 256))[col4];
                q1 = ((const float4*)(w1 + (size_t)(k0 + 1) * 256))[col4];
            }
        }
        // MMA chunk c
        {
            const int pbase = (c < 14) ? c * 8 : (c - 14) * 8;
            const uint2* Bbase = Bb + (c & 1) * BBUF;
            uint2 A0[4], A1[4];
            {
                const int r0 = mrow + gid;
                A0[0] = X2[r0 * SU2 + pbase + tig];
                A0[1] = X2[(r0 + 8) * SU2 + pbase + tig];
                A0[2] = X2[r0 * SU2 + pbase + tig + 4];
                A0[3] = X2[(r0 + 8) * SU2 + pbase + tig + 4];
                const int r1 = r0 + 16;
                A1[0] = X2[r1 * SU2 + pbase + tig];
                A1[1] = X2[(r1 + 8) * SU2 + pbase + tig];
                A1[2] = X2[r1 * SU2 + pbase + tig + 4];
                A1[3] = X2[(r1 + 8) * SU2 + pbase + tig + 4];
            }
            #pragma unroll
            for (int j = 0; j < 8; ++j) {
                const int col = nq + j * 8 + gid;
                const uint2 p0 = Bbase[tig * BST + col];
                const uint2 p1 = Bbase[(tig + 4) * BST + col];
                float* ac0 = &acc[j * 4];
                mma_f16(ac0, A0[0].x, A0[1].x, A0[2].x, A0[3].x, p0.x, p1.x);
                mma_f16(ac0, A0[0].x, A0[1].x, A0[2].x, A0[3].x, p0.y, p1.y);
                mma_f16(ac0, A0[0].y, A0[1].y, A0[2].y, A0[3].y, p0.x, p1.x);
                float* ac1 = &acc[32 + j * 4];
                mma_f16(ac1, A1[0].x, A1[1].x, A1[2].x, A1[3].x, p0.x, p1.x);
                mma_f16(ac1, A1[0].x, A1[1].x, A1[2].x, A1[3].x, p0.y, p1.y);
                mma_f16(ac1, A1[0].y, A1[1].y, A1[2].y, A1[3].y, p0.x, p1.x);
            }
        }
        __syncthreads();
        if (c == 13) {
            // H1 writeback: relu(+b0), split to hi/lo, own rows/cols only
            #pragma unroll
            for (int mt = 0; mt < 2; ++mt) {
                const int r0 = mrow + mt * 16 + gid;
                #pragma unroll
                for (int j = 0; j < 8; ++j) {
                    float* ac = &acc[(mt * 8 + j) * 4];
                    const int gc = nq + j * 8 + tig * 2;
                    const int pi = gc >> 1;
                    const float h00 = fmaxf(ac[0] + b0S[gc],   0.0f);
                    const float h01 = fmaxf(ac[1] + b0S[gc+1], 0.0f);
                    const float h10 = fmaxf(ac[2] + b0S[gc],   0.0f);
                    const float h11 = fmaxf(ac[3] + b0S[gc+1], 0.0f);
                    unsigned h, l;
                    split_pair(h00, h01, h, l); X2[r0 * SU2 + pi]       = make_uint2(h, l);
                    split_pair(h10, h11, h, l); X2[(r0 + 8) * SU2 + pi] = make_uint2(h, l);
                    ac[0] = 0.0f; ac[1] = 0.0f; ac[2] = 0.0f; ac[3] = 0.0f;
                }
            }
            __syncthreads();
        }
    }

    // ========== Layer 2 (fp32): relu(+b1) then @ w_out[256,4], quarter partials ==========
    {
        float pR[4][4];
        #pragma unroll
        for (int r = 0; r < 4; ++r)
            #pragma unroll
            for (int o = 0; o < 4; ++o) pR[r][o] = 0.0f;
        #pragma unroll
        for (int mt = 0; mt < 2; ++mt) {
            #pragma unroll
            for (int j = 0; j < 8; ++j) {
                float* ac = &acc[(mt * 8 + j) * 4];
                const int gc = nq + j * 8 + tig * 2;
                const float h00 = fmaxf(ac[0] + b1S[gc],   0.0f);
                const float h01 = fmaxf(ac[1] + b1S[gc+1], 0.0f);
                const float h10 = fmaxf(ac[2] + b1S[gc],   0.0f);
                const float h11 = fmaxf(ac[3] + b1S[gc+1], 0.0f);
                #pragma unroll
                for (int o = 0; o < 4; ++o) {
                    const float wv0 = WoutS[gc * 4 + o];
                    const float wv1 = WoutS[(gc + 1) * 4 + o];
                    pR[mt*2+0][o] += h00 * wv0 + h01 * wv1;
                    pR[mt*2+1][o] += h10 * wv0 + h11 * wv1;
                }
            }
        }
        #pragma unroll
        for (int m = 1; m <= 2; m <<= 1)
            #pragma unroll
            for (int r = 0; r < 4; ++r)
                #pragma unroll
                for (int o = 0; o < 4; ++o)
                    pR[r][o] += __shfl_xor_sync(0xffffffffu, pR[r][o], m);
        if (tig == 0) {
            const int qg = warp & 3;
            float* rb = rawS + qg * 512;
            #pragma unroll
            for (int o = 0; o < 4; ++o) {
                rb[(mrow + gid)      * 4 + o] = pR[0][o];
                rb[(mrow + gid + 8)  * 4 + o] = pR[1][o];
                rb[(mrow + gid + 16) * 4 + o] = pR[2][o];
                rb[(mrow + gid + 24) * 4 + o] = pR[3][o];
            }
        }
    }
    __syncthreads();

    // ---------------- Compositing: one thread per ray ----------------
    if (tid < 2) {
        const int g = blockIdx.x * 2 + tid;
        const float dx = rays_d[g*3], dy = rays_d[g*3+1], dz = rays_d[g*3+2];
        const float nd = sqrtf(dx*dx + dy*dy + dz*dz);
        float trans = 1.0f, r0 = 0.0f, r1 = 0.0f, r2 = 0.0f;
        const float ddist = 1.5f / 64.0f;
        for (int n = 0; n < 64; ++n) {
            const int row = tid * 64 + n;
            float raw[4];
            #pragma unroll
            for (int o = 0; o < 4; ++o)
                raw[o] = rawS[row*4+o] + rawS[512 + row*4+o]
                       + rawS[1024 + row*4+o] + rawS[1536 + row*4+o] + boS[o];
            const float sigma = fmaxf(raw[3], 0.0f);
            const float dist  = (n == 63) ? 1e10f : ddist;
            const float alpha = 1.0f - expf(-sigma * dist * nd);
            const float wgt   = alpha * trans;
            trans = trans * (1.0f - alpha + 1e-10f);
            r0 += wgt / (1.0f + expf(-raw[0]));
            r1 += wgt / (1.0f + expf(-raw[1]));
            r2 += wgt / (1.0f + expf(-raw[2]));
        }
        out[g*3+0] = r0; out[g*3+1] = r1; out[g*3+2] = r2;
    }
}

extern "C" void kernel_launch(void* const* d_in, const int* in_sizes, int n_in,
                              void* d_out, int out_size)
{
    const float* rays_o     = (const float*)d_in[0];
    const float* rays_d     = (const float*)d_in[1];
    const float* uv_feat    = (const float*)d_in[2];
    const float* transforms = (const float*)d_in[3];
    const float* w0         = (const float*)d_in[4];
    const float* b0         = (const float*)d_in[5];
    const float* w1         = (const float*)d_in[6];
    const float* b1         = (const float*)d_in[7];
    const float* w_out      = (const float*)d_in[8];
    const float* b_out      = (const float*)d_in[9];
    const int*   uv_idx     = (const int*)d_in[10];
    const int*   vox_idx    = (const int*)d_in[11];
    float* out = (float*)d_out;

    cudaFuncSetAttribute(vh_kernel, cudaFuncAttributeMaxDynamicSharedMemorySize, SMEM_BYTES);

    vh_kernel<<<8192, 512, SMEM_BYTES>>>(rays_o, rays_d, uv_feat, transforms,
                                         w0, b0, w1, b1, w_out, b_out,
                                         uv_idx, vox_idx, out);
}

// round 8
// speedup vs baseline: 1.5526x; 1.0176x over previous
#include <cuda_runtime.h>
#include <cuda_fp16.h>
#include <math.h>

// VoxelHuman fused: embed + gather -> 3xFP16 (m16n8k16) MLP -> compositing.
// Block = 2 rays = 128 points; grid 8192; 512 threads (16 warps).
// Warp tile 32x64. X/H1 pre-split f16 hi/lo. Double-buffered weight staging.
// R7: pointer-hoisted addressing + unroll-2 chunk loop (kills ALU address bloat).

#define SU2 132            // X2 row stride (uint2)
#define BST 268            // B buffer slot stride (uint2)
#define BBUF (8*BST)       // uint2 per B buffer

#define SMEM_BYTES (128*SU2*8 + 2*BBUF*8 + 4096 + 8192 + 768 + 1024 + 1024 + 32)

__device__ __forceinline__ unsigned pack_f16x2(float hi, float lo) {
    unsigned d;
    asm("cvt.rn.f16x2.f32 %0, %1, %2;" : "=r"(d) : "f"(hi), "f"(lo));
    return d;
}

// v0 -> low half (even k), v1 -> high half (odd k)
__device__ __forceinline__ void split_pair(float v0, float v1, unsigned& hi, unsigned& lo) {
    const unsigned h = pack_f16x2(v1, v0);
    const __half2 hh = *reinterpret_cast<const __half2*>(&h);
    const float f0 = __low2float(hh);
    const float f1 = __high2float(hh);
    lo = pack_f16x2(v1 - f1, v0 - f0);
    hi = h;
}

__device__ __forceinline__ void mma_f16(float* c,
                                        unsigned a0, unsigned a1, unsigned a2, unsigned a3,
                                        unsigned b0, unsigned b1) {
    asm("mma.sync.aligned.m16n8k16.row.col.f32.f16.f16.f32 "
        "{%0,%1,%2,%3},{%4,%5,%6,%7},{%8,%9},{%0,%1,%2,%3};\n"
        : "+f"(c[0]), "+f"(c[1]), "+f"(c[2]), "+f"(c[3])
        : "r"(a0), "r"(a1), "r"(a2), "r"(a3), "r"(b0), "r"(b1));
}

// Accurate fp32 sincos (Cody-Waite) — immune to --use_fast_math MUFU reduction.
__device__ __forceinline__ void sincos_acc(float x, float* sp, float* cp) {
    const float j = rintf(x * 0.636619772367581343f);
    const int   q = (int)j;
    float r = fmaf(j, -1.57079637050628662109375f, x);
    r = fmaf(j,  4.37113882867379290e-08f, r);
    r = fmaf(j,  1.71512451000590810e-15f, r);
    const float r2 = r * r;
    float sr = -1.9812813e-4f;
    sr = fmaf(sr, r2,  8.3333226e-3f);
    sr = fmaf(sr, r2, -1.6666667e-1f);
    sr = fmaf(sr * r2, r, r);
    float cr =  2.4372668e-5f;
    cr = fmaf(cr, r2, -1.3887316e-3f);
    cr = fmaf(cr, r2,  4.1666646e-2f);
    cr = fmaf(cr, r2, -5.0000000e-1f);
    cr = fmaf(cr, r2,  1.0f);
    float ss = (q & 1) ? cr : sr;
    float cc = (q & 1) ? sr : cr;
    if (q & 2) ss = -ss;
    if (((q & 2) != 0) != ((q & 1) != 0)) cc = -cc;
    *sp = ss; *cp = cc;
}

__global__ void __launch_bounds__(512, 1)
vh_kernel(const float* __restrict__ rays_o, const float* __restrict__ rays_d,
          const float* __restrict__ uv_feat, const float* __restrict__ transforms,
          const float* __restrict__ w0, const float* __restrict__ b0,
          const float* __restrict__ w1, const float* __restrict__ b1,
          const float* __restrict__ w_out, const float* __restrict__ b_out,
          const int* __restrict__ uv_idx, const int* __restrict__ vox_idx,
          float* __restrict__ out)
{
    extern __shared__ char smraw[];
    uint2* X2    = (uint2*)smraw;               // 128 x SU2 {hi,lo} f16x2 pairs
    uint2* Bb    = X2 + 128 * SU2;              // [2][8][BST] {hi,lo}
    float* WoutS = (float*)(Bb + 2 * BBUF);     // 1024
    float* rawS  = WoutS + 1024;                // 4 x 128 x 4
    float* TfS   = rawS + 2048;                 // 192
    float* b0S   = TfS + 192;                   // 256
    float* b1S   = b0S + 256;                   // 256
    float* boS   = b1S + 256;                   // 4 (pad 8)

    const int tid  = threadIdx.x;
    const int lane = tid & 31;
    const int warp = tid >> 5;           // 0..15
    const int gid  = lane >> 2;
    const int tig  = lane & 3;
    const int mrow = (warp >> 2) * 32;   // 32-row group
    const int nq   = (warp & 3) * 64;    // 64-col group

    const int kp   = tid >> 6;           // weight k-pair 0..7
    const int col4 = tid & 63;           // weight col-quad

    // stage small constants
    for (int i = tid; i < 192;  i += 512) TfS[i]   = transforms[i];
    for (int i = tid; i < 1024; i += 512) WoutS[i] = w_out[i];
    if (tid < 256) { b0S[tid] = b0[tid]; b1S[tid] = b1[tid]; }
    if (tid < 4) boS[tid] = b_out[tid];
    __syncthreads();

    const int base = blockIdx.x * 128;

    // hoisted weight cursors (per-thread column pre-baked)
    const float4* w0c = (const float4*)w0 + col4;
    const float4* w1c = (const float4*)w1 + col4;
    // layer-0 smem k layout: [0..62]=w0 rows 0..62, 63=zero, [64..211]=w0 rows 63..210
    auto ldw0 = [&](int k) -> float4 {
        if (k < 63)  return w0c[(size_t)k * 64];
        if (k >= 64 && k < 212) return w0c[(size_t)(k - 1) * 64];
        return make_float4(0.f, 0.f, 0.f, 0.f);
    };

    float4 q0, q1;   // prefetched next chunk (rows k0, k0+1 of chunk)
    q0 = ldw0(2 * kp);
    q1 = ldw0(2 * kp + 1);

    // ---------------- Phase 1: build X (pre-split hi/lo pairs) ----------------
    if (tid < 128) {
        const int p = tid;
        const int n = p & 63;
        const int g = blockIdx.x * 2 + (p >> 6);
        const float z = 0.5f + (float)n * (1.5f / 64.0f);
        const float px = rays_o[g*3+0] + rays_d[g*3+0] * z;
        const float py = rays_o[g*3+1] + rays_d[g*3+1] * z;
        const float pz = rays_o[g*3+2] + rays_d[g*3+2] * z;
        const int vox = vox_idx[base + p];
        const float* T = TfS + vox * 12;
        float xv[64];
        xv[0] = T[0]*px + T[1]*py + T[2]*pz  + T[3];
        xv[1] = T[4]*px + T[5]*py + T[6]*pz  + T[7];
        xv[2] = T[8]*px + T[9]*py + T[10]*pz + T[11];
        float f = 1.0f;
        #pragma unroll
        for (int k = 0; k < 10; ++k) {
            float s, c;
            sincos_acc(xv[0] * f, &s, &c); xv[3+6*k+0] = s; xv[3+6*k+3] = c;
            sincos_acc(xv[1] * f, &s, &c); xv[3+6*k+1] = s; xv[3+6*k+4] = c;
            sincos_acc(xv[2] * f, &s, &c); xv[3+6*k+2] = s; xv[3+6*k+5] = c;
            f *= 2.0f;
        }
        xv[63] = 0.0f;
        uint2* xr = X2 + p * SU2;
        #pragma unroll
        for (int q = 0; q < 32; ++q) {
            unsigned h, l;
            split_pair(xv[2*q], xv[2*q+1], h, l);
            xr[q] = make_uint2(h, l);
        }
        #pragma unroll
        for (int q = 106; q < 112; ++q) xr[q] = make_uint2(0u, 0u);
    } else {
        // 384 threads gather uv_feat (148 ch): 3 threads per point, split+store pairs
        const int t3  = tid - 128;
        const int p   = t3 & 127;
        const int sub = t3 >> 7;
        const int g   = blockIdx.x * 2 + (p >> 6);
        const int bi  = g >> 13;
        const int uvi = uv_idx[base + p];
        const float4* src =
            (const float4*)(uv_feat + ((size_t)bi * 65536 + (size_t)uvi) * 148);
        uint2* xr = X2 + p * SU2;
        for (int q = sub; q < 37; q += 3) {
            const float4 v = src[q];
            unsigned h0, l0, h1, l1;
            split_pair(v.x, v.y, h0, l0);
            split_pair(v.z, v.w, h1, l1);
            *(uint4*)(xr + 32 + 2 * q) = make_uint4(h0, l0, h1, l1);
        }
    }

    // stage chunk 0 into buf 0
    uint4* stg = (uint4*)(Bb + kp * BST + col4 * 4);    // buffer 1 at +BBUF/2 uint4
    {
        unsigned h0,l0,h1,l1,h2,l2,h3,l3;
        split_pair(q0.x, q1.x, h0, l0);
        split_pair(q0.y, q1.y, h1, l1);
        split_pair(q0.z, q1.z, h2, l2);
        split_pair(q0.w, q1.w, h3, l3);
        stg[0] = make_uint4(h0, l0, h1, l1);
        stg[1] = make_uint4(h2, l2, h3, l3);
    }
    // prefetch chunk 1
    q0 = ldw0(16 + 2 * kp);
    q1 = ldw0(16 + 2 * kp + 1);

    float acc[64];
    #pragma unroll
    for (int i = 0; i < 64; ++i) acc[i] = 0.0f;

    // hoisted A-row cursors (advance +8 per chunk, reset at layer switch)
    const uint2* rA0base = X2 + (mrow + gid) * SU2 + tig;
    const uint2* rA0 = rA0base;
    const uint2* rA1 = rA0base + 8  * SU2;
    const uint2* rA2 = rA0base + 16 * SU2;
    const uint2* rA3 = rA0base + 24 * SU2;
    // hoisted B-read cursors (j*8 and buffer offset are immediates under unroll-2)
    const uint2* bB0 = Bb + tig * BST + nq + gid;
    const uint2* bB1 = Bb + (tig + 4) * BST + nq + gid;

    __syncthreads();

    // ================= Unified chunk loop: 14 (layer0) + 16 (layer1) =================
    #pragma unroll 2
    for (int c = 0; c < 30; ++c) {
        // stage prefetched chunk c+1 into the other buffer
        if (c < 29) {
            unsigned h0,l0,h1,l1,h2,l2,h3,l3;
            split_pair(q0.x, q1.x, h0, l0);
            split_pair(q0.y, q1.y, h1, l1);
            split_pair(q0.z, q1.z, h2, l2);
            split_pair(q0.w, q1.w, h3, l3);
            uint4* d = stg + ((c + 1) & 1) * (BBUF / 2);
            d[0] = make_uint4(h0, l0, h1, l1);
            d[1] = make_uint4(h2, l2, h3, l3);
        }
        // prefetch chunk c+2
        if (c < 28) {
            const int nc = c + 2;
            if (nc < 14) {
                const int k0 = nc * 16 + 2 * kp;
                q0 = ldw0(k0);
                q1 = ldw0(k0 + 1);
            } else {
                const size_t k0 = (size_t)((nc - 14) * 16 + 2 * kp) * 64;
                q0 = w1c[k0];
                q1 = w1c[k0 + 64];
            }
        }
        // MMA chunk c
        {
            const uint2* Bb0 = bB0 + (c & 1) * BBUF;
            const uint2* Bb1 = bB1 + (c & 1) * BBUF;
            uint2 A0[4], A1[4];
            A0[0] = rA0[0]; A0[1] = rA1[0]; A0[2] = rA0[4]; A0[3] = rA1[4];
            A1[0] = rA2[0]; A1[1] = rA3[0]; A1[2] = rA2[4]; A1[3] = rA3[4];
            #pragma unroll
            for (int j = 0; j < 8; ++j) {
                const uint2 p0 = Bb0[j * 8];
                const uint2 p1 = Bb1[j * 8];
                float* ac0 = &acc[j * 4];
                mma_f16(ac0, A0[0].x, A0[1].x, A0[2].x, A0[3].x, p0.x, p1.x);
                mma_f16(ac0, A0[0].x, A0[1].x, A0[2].x, A0[3].x, p0.y, p1.y);
                mma_f16(ac0, A0[0].y, A0[1].y, A0[2].y, A0[3].y, p0.x, p1.x);
                float* ac1 = &acc[32 + j * 4];
                mma_f16(ac1, A1[0].x, A1[1].x, A1[2].x, A1[3].x, p0.x, p1.x);
                mma_f16(ac1, A1[0].x, A1[1].x, A1[2].x, A1[3].x, p0.y, p1.y);
                mma_f16(ac1, A1[0].y, A1[1].y, A1[2].y, A1[3].y, p0.x, p1.x);
            }
        }
        __syncthreads();
        if (c == 13) {
            // H1 writeback: relu(+b0), split to hi/lo, own rows/cols only
            #pragma unroll
            for (int mt = 0; mt < 2; ++mt) {
                const int r0 = mrow + mt * 16 + gid;
                #pragma unroll
                for (int j = 0; j < 8; ++j) {
                    float* ac = &acc[(mt * 8 + j) * 4];
                    const int gc = nq + j * 8 + tig * 2;
                    const int pi = gc >> 1;
                    const float h00 = fmaxf(ac[0] + b0S[gc],   0.0f);
                    const float h01 = fmaxf(ac[1] + b0S[gc+1], 0.0f);
                    const float h10 = fmaxf(ac[2] + b0S[gc],   0.0f);
                    const float h11 = fmaxf(ac[3] + b0S[gc+1], 0.0f);
                    unsigned h, l;
                    split_pair(h00, h01, h, l); X2[r0 * SU2 + pi]       = make_uint2(h, l);
                    split_pair(h10, h11, h, l); X2[(r0 + 8) * SU2 + pi] = make_uint2(h, l);
                    ac[0] = 0.0f; ac[1] = 0.0f; ac[2] = 0.0f; ac[3] = 0.0f;
                }
            }
            __syncthreads();
            rA0 = rA0base;            rA1 = rA0base + 8  * SU2;
            rA2 = rA0base + 16 * SU2; rA3 = rA0base + 24 * SU2;
        } else {
            rA0 += 8; rA1 += 8; rA2 += 8; rA3 += 8;
        }
    }

    // ========== Layer 2 (fp32): relu(+b1) then @ w_out[256,4], quarter partials ==========
    {
        float pR[4][4];
        #pragma unroll
        for (int r = 0; r < 4; ++r)
            #pragma unroll
            for (int o = 0; o < 4; ++o) pR[r][o] = 0.0f;
        #pragma unroll
        for (int mt = 0; mt < 2; ++mt) {
            #pragma unroll
            for (int j = 0; j < 8; ++j) {
                float* ac = &acc[(mt * 8 + j) * 4];
                const int gc = nq + j * 8 + tig * 2;
                const float h00 = fmaxf(ac[0] + b1S[gc],   0.0f);
                const float h01 = fmaxf(ac[1] + b1S[gc+1], 0.0f);
                const float h10 = fmaxf(ac[2] + b1S[gc],   0.0f);
                const float h11 = fmaxf(ac[3] + b1S[gc+1], 0.0f);
                #pragma unroll
                for (int o = 0; o < 4; ++o) {
                    const float wv0 = WoutS[gc * 4 + o];
                    const float wv1 = WoutS[(gc + 1) * 4 + o];
                    pR[mt*2+0][o] += h00 * wv0 + h01 * wv1;
                    pR[mt*2+1][o] += h10 * wv0 + h11 * wv1;
                }
            }
        }
        #pragma unroll
        for (int m = 1; m <= 2; m <<= 1)
            #pragma unroll
            for (int r = 0; r < 4; ++r)
                #pragma unroll
                for (int o = 0; o < 4; ++o)
                    pR[r][o] += __shfl_xor_sync(0xffffffffu, pR[r][o], m);
        if (tig == 0) {
            const int qg = warp & 3;
            float* rb = rawS + qg * 512;
            #pragma unroll
            for (int o = 0; o < 4; ++o) {
                rb[(mrow + gid)      * 4 + o] = pR[0][o];
                rb[(mrow + gid + 8)  * 4 + o] = pR[1][o];
                rb[(mrow + gid + 16) * 4 + o] = pR[2][o];
                rb[(mrow + gid + 24) * 4 + o] = pR[3][o];
            }
        }
    }
    __syncthreads();

    // ---------------- Compositing: one thread per ray ----------------
    if (tid < 2) {
        const int g = blockIdx.x * 2 + tid;
        const float dx = rays_d[g*3], dy = rays_d[g*3+1], dz = rays_d[g*3+2];
        const float nd = sqrtf(dx*dx + dy*dy + dz*dz);
        float trans = 1.0f, r0 = 0.0f, r1 = 0.0f, r2 = 0.0f;
        const float ddist = 1.5f / 64.0f;
        for (int n = 0; n < 64; ++n) {
            const int row = tid * 64 + n;
            float raw[4];
            #pragma unroll
            for (int o = 0; o < 4; ++o)
                raw[o] = rawS[row*4+o] + rawS[512 + row*4+o]
                       + rawS[1024 + row*4+o] + rawS[1536 + row*4+o] + boS[o];
            const float sigma = fmaxf(raw[3], 0.0f);
            const float dist  = (n == 63) ? 1e10f : ddist;
            const float alpha = 1.0f - expf(-sigma * dist * nd);
            const float wgt   = alpha * trans;
            trans = trans * (1.0f - alpha + 1e-10f);
            r0 += wgt / (1.0f + expf(-raw[0]));
            r1 += wgt / (1.0f + expf(-raw[1]));
            r2 += wgt / (1.0f + expf(-raw[2]));
        }
        out[g*3+0] = r0; out[g*3+1] = r1; out[g*3+2] = r2;
    }
}

extern "C" void kernel_launch(void* const* d_in, const int* in_sizes, int n_in,
                              void* d_out, int out_size)
{
    const float* rays_o     = (const float*)d_in[0];
    const float* rays_d     = (const float*)d_in[1];
    const float* uv_feat    = (const float*)d_in[2];
    const float* transforms = (const float*)d_in[3];
    const float* w0         = (const float*)d_in[4];
    const float* b0         = (const float*)d_in[5];
    const float* w1         = (const float*)d_in[6];
    const float* b1         = (const float*)d_in[7];
    const float* w_out      = (const float*)d_in[8];
    const float* b_out      = (const float*)d_in[9];
    const int*   uv_idx     = (const int*)d_in[10];
    const int*   vox_idx    = (const int*)d_in[11];
    float* out = (float*)d_out;

    cudaFuncSetAttribute(vh_kernel, cudaFuncAttributeMaxDynamicSharedMemorySize, SMEM_BYTES);

    vh_kernel<<<8192, 512, SMEM_BYTES>>>(rays_o, rays_d, uv_feat, transforms,
                                         w0, b0, w1, b1, w_out, b_out,
                                         uv_idx, vox_idx, out);
}

// round 9
// speedup vs baseline: 1.6890x; 1.0878x over previous
#include <cuda_runtime.h>
#include <cuda_fp16.h>
#include <math.h>

// VoxelHuman fused: embed + gather -> 3xFP16 (m16n8k16) MLP -> compositing.
// R8: block = 1 ray = 64 points, 256 threads (8 warps), smem ~108KB ->
//     2 blocks/SM co-resident (decoupled barriers hide latency).
// Warp tile 16x128. X/H1 pre-split f16 hi/lo. Double-buffered weight staging.

#define SU2 132            // X2 row stride (uint2)
#define BST 268            // B buffer slot stride (uint2)
#define BBUF (8*BST)       // uint2 per B buffer

#define SMEM_BYTES (64*SU2*8 + 2*BBUF*8 + 4096 + 2048 + 768 + 1024 + 1024 + 32)

__device__ __forceinline__ unsigned pack_f16x2(float hi, float lo) {
    unsigned d;
    asm("cvt.rn.f16x2.f32 %0, %1, %2;" : "=r"(d) : "f"(hi), "f"(lo));
    return d;
}

// v0 -> low half (even k), v1 -> high half (odd k)
__device__ __forceinline__ void split_pair(float v0, float v1, unsigned& hi, unsigned& lo) {
    const unsigned h = pack_f16x2(v1, v0);
    const __half2 hh = *reinterpret_cast<const __half2*>(&h);
    const float f0 = __low2float(hh);
    const float f1 = __high2float(hh);
    lo = pack_f16x2(v1 - f1, v0 - f0);
    hi = h;
}

__device__ __forceinline__ void mma_f16(float* c,
                                        unsigned a0, unsigned a1, unsigned a2, unsigned a3,
                                        unsigned b0, unsigned b1) {
    asm("mma.sync.aligned.m16n8k16.row.col.f32.f16.f16.f32 "
        "{%0,%1,%2,%3},{%4,%5,%6,%7},{%8,%9},{%0,%1,%2,%3};\n"
        : "+f"(c[0]), "+f"(c[1]), "+f"(c[2]), "+f"(c[3])
        : "r"(a0), "r"(a1), "r"(a2), "r"(a3), "r"(b0), "r"(b1));
}

// Accurate fp32 sincos (Cody-Waite) — immune to --use_fast_math MUFU reduction.
__device__ __forceinline__ void sincos_acc(float x, float* sp, float* cp) {
    const float j = rintf(x * 0.636619772367581343f);
    const int   q = (int)j;
    float r = fmaf(j, -1.57079637050628662109375f, x);
    r = fmaf(j,  4.37113882867379290e-08f, r);
    r = fmaf(j,  1.71512451000590810e-15f, r);
    const float r2 = r * r;
    float sr = -1.9812813e-4f;
    sr = fmaf(sr, r2,  8.3333226e-3f);
    sr = fmaf(sr, r2, -1.6666667e-1f);
    sr = fmaf(sr * r2, r, r);
    float cr =  2.4372668e-5f;
    cr = fmaf(cr, r2, -1.3887316e-3f);
    cr = fmaf(cr, r2,  4.1666646e-2f);
    cr = fmaf(cr, r2, -5.0000000e-1f);
    cr = fmaf(cr, r2,  1.0f);
    float ss = (q & 1) ? cr : sr;
    float cc = (q & 1) ? sr : cr;
    if (q & 2) ss = -ss;
    if (((q & 2) != 0) != ((q & 1) != 0)) cc = -cc;
    *sp = ss; *cp = cc;
}

__global__ void __launch_bounds__(256, 2)
vh_kernel(const float* __restrict__ rays_o, const float* __restrict__ rays_d,
          const float* __restrict__ uv_feat, const float* __restrict__ transforms,
          const float* __restrict__ w0, const float* __restrict__ b0,
          const float* __restrict__ w1, const float* __restrict__ b1,
          const float* __restrict__ w_out, const float* __restrict__ b_out,
          const int* __restrict__ uv_idx, const int* __restrict__ vox_idx,
          float* __restrict__ out)
{
    extern __shared__ char smraw[];
    uint2* X2    = (uint2*)smraw;               // 64 x SU2 {hi,lo} f16x2 pairs
    uint2* Bb    = X2 + 64 * SU2;               // [2][8][BST] {hi,lo}
    float* WoutS = (float*)(Bb + 2 * BBUF);     // 1024
    float* rawS  = WoutS + 1024;                // 2 x 64 x 4
    float* TfS   = rawS + 512;                  // 192
    float* b0S   = TfS + 192;                   // 256
    float* b1S   = b0S + 256;                   // 256
    float* boS   = b1S + 256;                   // 4 (pad 8)

    const int tid  = threadIdx.x;
    const int lane = tid & 31;
    const int warp = tid >> 5;           // 0..7
    const int gid  = lane >> 2;
    const int tig  = lane & 3;
    const int mrow = (warp >> 1) * 16;   // 16-row group
    const int nh   = (warp & 1) * 128;   // 128-col half

    const int kp   = tid >> 5;           // weight k-pair 0..7
    const int c8   = tid & 31;           // weight col-quad (and +32)

    // stage small constants
    for (int i = tid; i < 192;  i += 256) TfS[i]   = transforms[i];
    for (int i = tid; i < 1024; i += 256) WoutS[i] = w_out[i];
    b0S[tid] = b0[tid];
    b1S[tid] = b1[tid];
    if (tid < 4) boS[tid] = b_out[tid];
    __syncthreads();

    const int g    = blockIdx.x;         // ray index
    const int base = g * 64;             // flat point base

    // hoisted weight cursors (two column quads per thread)
    const float4* w0a = (const float4*)w0 + c8;
    const float4* w0b = w0a + 32;
    const float4* w1a = (const float4*)w1 + c8;
    const float4* w1b = w1a + 32;
    // layer-0 smem k layout: [0..62]=w0 rows 0..62, 63=zero, [64..211]=w0 rows 63..210
    auto ldw0 = [](const float4* cur, int k) -> float4 {
        if (k < 63)  return cur[(size_t)k * 64];
        if (k >= 64 && k < 212) return cur[(size_t)(k - 1) * 64];
        return make_float4(0.f, 0.f, 0.f, 0.f);
    };

    float4 qa0, qa1, qb0, qb1;   // prefetched next chunk (rows 2kp, 2kp+1; quads c8, c8+32)
    qa0 = ldw0(w0a, 2 * kp);  qa1 = ldw0(w0a, 2 * kp + 1);
    qb0 = ldw0(w0b, 2 * kp);  qb1 = ldw0(w0b, 2 * kp + 1);

    // ---------------- Phase 1: build X (pre-split hi/lo pairs) ----------------
    if (tid < 64) {
        const int p = tid;                 // sample index 0..63
        const float z = 0.5f + (float)p * (1.5f / 64.0f);
        const float px = rays_o[g*3+0] + rays_d[g*3+0] * z;
        const float py = rays_o[g*3+1] + rays_d[g*3+1] * z;
        const float pz = rays_o[g*3+2] + rays_d[g*3+2] * z;
        const int vox = vox_idx[base + p];
        const float* T = TfS + vox * 12;
        float xv[64];
        xv[0] = T[0]*px + T[1]*py + T[2]*pz  + T[3];
        xv[1] = T[4]*px + T[5]*py + T[6]*pz  + T[7];
        xv[2] = T[8]*px + T[9]*py + T[10]*pz + T[11];
        float f = 1.0f;
        #pragma unroll
        for (int k = 0; k < 10; ++k) {
            float s, c;
            sincos_acc(xv[0] * f, &s, &c); xv[3+6*k+0] = s; xv[3+6*k+3] = c;
            sincos_acc(xv[1] * f, &s, &c); xv[3+6*k+1] = s; xv[3+6*k+4] = c;
            sincos_acc(xv[2] * f, &s, &c); xv[3+6*k+2] = s; xv[3+6*k+5] = c;
            f *= 2.0f;
        }
        xv[63] = 0.0f;
        uint2* xr = X2 + p * SU2;
        #pragma unroll
        for (int q = 0; q < 32; ++q) {
            unsigned h, l;
            split_pair(xv[2*q], xv[2*q+1], h, l);
            xr[q] = make_uint2(h, l);
        }
        #pragma unroll
        for (int q = 106; q < 112; ++q) xr[q] = make_uint2(0u, 0u);
    } else {
        // 192 threads gather uv_feat (148 ch): 3 threads per point
        const int t3  = tid - 64;
        const int p   = t3 & 63;
        const int sub = t3 >> 6;        // 0..2
        const int bi  = g >> 13;        // batch index (8192 rays per batch)
        const int uvi = uv_idx[base + p];
        const float4* src =
            (const float4*)(uv_feat + ((size_t)bi * 65536 + (size_t)uvi) * 148);
        uint2* xr = X2 + p * SU2;
        for (int q = sub; q < 37; q += 3) {
            const float4 v = src[q];
            unsigned h0, l0, h1, l1;
            split_pair(v.x, v.y, h0, l0);
            split_pair(v.z, v.w, h1, l1);
            *(uint4*)(xr + 32 + 2 * q) = make_uint4(h0, l0, h1, l1);
        }
    }

    // stage chunk 0 into buf 0
    uint4* stgA = (uint4*)(Bb + kp * BST + c8 * 4);
    uint4* stgB = (uint4*)(Bb + kp * BST + (c8 + 32) * 4);
    {
        unsigned h0,l0,h1,l1,h2,l2,h3,l3;
        split_pair(qa0.x, qa1.x, h0, l0); split_pair(qa0.y, qa1.y, h1, l1);
        split_pair(qa0.z, qa1.z, h2, l2); split_pair(qa0.w, qa1.w, h3, l3);
        stgA[0] = make_uint4(h0, l0, h1, l1);
        stgA[1] = make_uint4(h2, l2, h3, l3);
        split_pair(qb0.x, qb1.x, h0, l0); split_pair(qb0.y, qb1.y, h1, l1);
        split_pair(qb0.z, qb1.z, h2, l2); split_pair(qb0.w, qb1.w, h3, l3);
        stgB[0] = make_uint4(h0, l0, h1, l1);
        stgB[1] = make_uint4(h2, l2, h3, l3);
    }
    // prefetch chunk 1
    qa0 = ldw0(w0a, 16 + 2 * kp);  qa1 = ldw0(w0a, 16 + 2 * kp + 1);
    qb0 = ldw0(w0b, 16 + 2 * kp);  qb1 = ldw0(w0b, 16 + 2 * kp + 1);

    float acc[64];
    #pragma unroll
    for (int i = 0; i < 64; ++i) acc[i] = 0.0f;

    // hoisted A-row cursors (advance +8 per chunk, reset at layer switch)
    const uint2* rA0base = X2 + (mrow + gid) * SU2 + tig;
    const uint2* rA0 = rA0base;
    const uint2* rA1 = rA0base + 8 * SU2;
    // hoisted B-read cursors
    const uint2* bB0 = Bb + tig * BST + nh + gid;
    const uint2* bB1 = Bb + (tig + 4) * BST + nh + gid;

    __syncthreads();

    // ================= Unified chunk loop: 14 (layer0) + 16 (layer1) =================
    #pragma unroll 2
    for (int c = 0; c < 30; ++c) {
        // stage prefetched chunk c+1 into the other buffer
        if (c < 29) {
            unsigned h0,l0,h1,l1,h2,l2,h3,l3;
            uint4* dA = stgA + ((c + 1) & 1) * (BBUF / 2);
            uint4* dB = stgB + ((c + 1) & 1) * (BBUF / 2);
            split_pair(qa0.x, qa1.x, h0, l0); split_pair(qa0.y, qa1.y, h1, l1);
            split_pair(qa0.z, qa1.z, h2, l2); split_pair(qa0.w, qa1.w, h3, l3);
            dA[0] = make_uint4(h0, l0, h1, l1);
            dA[1] = make_uint4(h2, l2, h3, l3);
            split_pair(qb0.x, qb1.x, h0, l0); split_pair(qb0.y, qb1.y, h1, l1);
            split_pair(qb0.z, qb1.z, h2, l2); split_pair(qb0.w, qb1.w, h3, l3);
            dB[0] = make_uint4(h0, l0, h1, l1);
            dB[1] = make_uint4(h2, l2, h3, l3);
        }
        // prefetch chunk c+2
        if (c < 28) {
            const int nc = c + 2;
            if (nc < 14) {
                const int k0 = nc * 16 + 2 * kp;
                qa0 = ldw0(w0a, k0);  qa1 = ldw0(w0a, k0 + 1);
                qb0 = ldw0(w0b, k0);  qb1 = ldw0(w0b, k0 + 1);
            } else {
                const size_t k0 = (size_t)((nc - 14) * 16 + 2 * kp) * 64;
                qa0 = w1a[k0];  qa1 = w1a[k0 + 64];
                qb0 = w1b[k0];  qb1 = w1b[k0 + 64];
            }
        }
        // MMA chunk c (warp tile 16 x 128)
        {
            const uint2* Bc0 = bB0 + (c & 1) * BBUF;
            const uint2* Bc1 = bB1 + (c & 1) * BBUF;
            uint2 A0[4];
            A0[0] = rA0[0]; A0[1] = rA1[0]; A0[2] = rA0[4]; A0[3] = rA1[4];
            #pragma unroll
            for (int j = 0; j < 16; ++j) {
                const uint2 p0 = Bc0[j * 8];
                const uint2 p1 = Bc1[j * 8];
                float* ac = &acc[j * 4];
                mma_f16(ac, A0[0].x, A0[1].x, A0[2].x, A0[3].x, p0.x, p1.x);
                mma_f16(ac, A0[0].x, A0[1].x, A0[2].x, A0[3].x, p0.y, p1.y);
                mma_f16(ac, A0[0].y, A0[1].y, A0[2].y, A0[3].y, p0.x, p1.x);
            }
        }
        __syncthreads();
        if (c == 13) {
            // H1 writeback: relu(+b0), split to hi/lo, own rows/cols only
            const int r0 = mrow + gid;
            #pragma unroll
            for (int j = 0; j < 16; ++j) {
                float* ac = &acc[j * 4];
                const int gc = nh + j * 8 + tig * 2;
                const int pi = gc >> 1;
                const float h00 = fmaxf(ac[0] + b0S[gc],   0.0f);
                const float h01 = fmaxf(ac[1] + b0S[gc+1], 0.0f);
                const float h10 = fmaxf(ac[2] + b0S[gc],   0.0f);
                const float h11 = fmaxf(ac[3] + b0S[gc+1], 0.0f);
                unsigned h, l;
                split_pair(h00, h01, h, l); X2[r0 * SU2 + pi]       = make_uint2(h, l);
                split_pair(h10, h11, h, l); X2[(r0 + 8) * SU2 + pi] = make_uint2(h, l);
                ac[0] = 0.0f; ac[1] = 0.0f; ac[2] = 0.0f; ac[3] = 0.0f;
            }
            __syncthreads();
            rA0 = rA0base;
            rA1 = rA0base + 8 * SU2;
        } else {
            rA0 += 8; rA1 += 8;
        }
    }

    // ========== Layer 2 (fp32): relu(+b1) then @ w_out[256,4], half partials ==========
    {
        float pA[4] = {0,0,0,0}, pB[4] = {0,0,0,0};
        #pragma unroll
        for (int j = 0; j < 16; ++j) {
            float* ac = &acc[j * 4];
            const int gc = nh + j * 8 + tig * 2;
            const float h00 = fmaxf(ac[0] + b1S[gc],   0.0f);
            const float h01 = fmaxf(ac[1] + b1S[gc+1], 0.0f);
            const float h10 = fmaxf(ac[2] + b1S[gc],   0.0f);
            const float h11 = fmaxf(ac[3] + b1S[gc+1], 0.0f);
            #pragma unroll
            for (int o = 0; o < 4; ++o) {
                const float wv0 = WoutS[gc * 4 + o];
                const float wv1 = WoutS[(gc + 1) * 4 + o];
                pA[o] += h00 * wv0 + h01 * wv1;
                pB[o] += h10 * wv0 + h11 * wv1;
            }
        }
        #pragma unroll
        for (int m = 1; m <= 2; m <<= 1) {
            #pragma unroll
            for (int o = 0; o < 4; ++o) {
                pA[o] += __shfl_xor_sync(0xffffffffu, pA[o], m);
                pB[o] += __shfl_xor_sync(0xffffffffu, pB[o], m);
            }
        }
        if (tig == 0) {
            float* rb = rawS + (warp & 1) * 256;
            #pragma unroll
            for (int o = 0; o < 4; ++o) {
                rb[(mrow + gid)     * 4 + o] = pA[o];
                rb[(mrow + gid + 8) * 4 + o] = pB[o];
            }
        }
    }
    __syncthreads();

    // ---------------- Compositing: one thread (1 ray/block) ----------------
    if (tid == 0) {
        const float dx = rays_d[g*3], dy = rays_d[g*3+1], dz = rays_d[g*3+2];
        const float nd = sqrtf(dx*dx + dy*dy + dz*dz);
        float trans = 1.0f, r0 = 0.0f, r1 = 0.0f, r2 = 0.0f;
        const float ddist = 1.5f / 64.0f;
        for (int n = 0; n < 64; ++n) {
            float raw[4];
            #pragma unroll
            for (int o = 0; o < 4; ++o)
                raw[o] = rawS[n*4+o] + rawS[256 + n*4+o] + boS[o];
            const float sigma = fmaxf(raw[3], 0.0f);
            const float dist  = (n == 63) ? 1e10f : ddist;
            const float alpha = 1.0f - expf(-sigma * dist * nd);
            const float wgt   = alpha * trans;
            trans = trans * (1.0f - alpha + 1e-10f);
            r0 += wgt / (1.0f + expf(-raw[0]));
            r1 += wgt / (1.0f + expf(-raw[1]));
            r2 += wgt / (1.0f + expf(-raw[2]));
        }
        out[g*3+0] = r0; out[g*3+1] = r1; out[g*3+2] = r2;
    }
}

extern "C" void kernel_launch(void* const* d_in, const int* in_sizes, int n_in,
                              void* d_out, int out_size)
{
    const float* rays_o     = (const float*)d_in[0];
    const float* rays_d     = (const float*)d_in[1];
    const float* uv_feat    = (const float*)d_in[2];
    const float* transforms = (const float*)d_in[3];
    const float* w0         = (const float*)d_in[4];
    const float* b0         = (const float*)d_in[5];
    const float* w1         = (const float*)d_in[6];
    const float* b1         = (const float*)d_in[7];
    const float* w_out      = (const float*)d_in[8];
    const float* b_out      = (const float*)d_in[9];
    const int*   uv_idx     = (const int*)d_in[10];
    const int*   vox_idx    = (const int*)d_in[11];
    float* out = (float*)d_out;

    cudaFuncSetAttribute(vh_kernel, cudaFuncAttributeMaxDynamicSharedMemorySize, SMEM_BYTES);

    vh_kernel<<<16384, 256, SMEM_BYTES>>>(rays_o, rays_d, uv_feat, transforms,
                                          w0, b0, w1, b1, w_out, b_out,
                                          uv_idx, vox_idx, out);
}